// round 16
// baseline (speedup 1.0000x reference)
#include <cuda_runtime.h>
#include <cuda_bf16.h>
#include <cstdint>

#define BSZ    2
#define SEQ    4096
#define EMBED  1024
#define NHEAD  16
#define HDIM   64
#define WIN    256
#define MTOT   (BSZ*SEQ)

// Split-bf16 Q/K/V scratch for attention
__device__ __nv_bfloat16 g_qh[(size_t)MTOT * EMBED];
__device__ __nv_bfloat16 g_ql[(size_t)MTOT * EMBED];
__device__ __nv_bfloat16 g_kh[(size_t)MTOT * EMBED];
__device__ __nv_bfloat16 g_kl[(size_t)MTOT * EMBED];
__device__ __nv_bfloat16 g_vh[(size_t)MTOT * EMBED];
__device__ __nv_bfloat16 g_vl[(size_t)MTOT * EMBED];
// Pre-split GEMM inputs: H [m][k]; W transposed [z][n][k]
__device__ __nv_bfloat16 g_hh[(size_t)MTOT * EMBED];
__device__ __nv_bfloat16 g_hl[(size_t)MTOT * EMBED];
__device__ __nv_bfloat16 g_wth[(size_t)3 * EMBED * EMBED];
__device__ __nv_bfloat16 g_wtl[(size_t)3 * EMBED * EMBED];

// ---------------------------------------------------------------------------
// Helpers
// ---------------------------------------------------------------------------
__device__ __forceinline__ uint32_t smem_u32(const void* p) {
    uint32_t a;
    asm("{ .reg .u64 t; cvta.to.shared.u64 t, %1; cvt.u32.u64 %0, t; }"
        : "=r"(a) : "l"(p));
    return a;
}
__device__ __forceinline__ void ldsm4(uint32_t* r, uint32_t addr) {
    asm volatile("ldmatrix.sync.aligned.m8n8.x4.shared.b16 {%0,%1,%2,%3}, [%4];"
        : "=r"(r[0]), "=r"(r[1]), "=r"(r[2]), "=r"(r[3]) : "r"(addr));
}
__device__ __forceinline__ void ldsm4t(uint32_t* r, uint32_t addr) {
    asm volatile("ldmatrix.sync.aligned.m8n8.x4.trans.shared.b16 {%0,%1,%2,%3}, [%4];"
        : "=r"(r[0]), "=r"(r[1]), "=r"(r[2]), "=r"(r[3]) : "r"(addr));
}
__device__ __forceinline__ void mma16816(float* c, const uint32_t* a,
                                         const uint32_t* b) {
    asm volatile(
        "mma.sync.aligned.m16n8k16.row.col.f32.bf16.bf16.f32 "
        "{%0,%1,%2,%3}, {%4,%5,%6,%7}, {%8,%9}, {%0,%1,%2,%3};"
        : "+f"(c[0]), "+f"(c[1]), "+f"(c[2]), "+f"(c[3])
        : "r"(a[0]), "r"(a[1]), "r"(a[2]), "r"(a[3]), "r"(b[0]), "r"(b[1]));
}
__device__ __forceinline__ void cpa16(uint32_t s, const void* g) {
    asm volatile(
        "{ .reg .u64 gp; cvta.to.global.u64 gp, %1;"
        "  cp.async.ca.shared.global [%0], [gp], 16; }"
        :: "r"(s), "l"(g));
}

__device__ __forceinline__ void split1(float x, __nv_bfloat16& h, __nv_bfloat16& l) {
    h = __float2bfloat16(x);
    l = __float2bfloat16(x - __bfloat162float(h));
}
__device__ __forceinline__ void split2(float x0, float x1, uint32_t& h, uint32_t& l) {
    __nv_bfloat16 h0, l0, h1, l1;
    split1(x0, h0, l0);
    split1(x1, h1, l1);
    h = (uint32_t)__bfloat16_as_ushort(h0) | ((uint32_t)__bfloat16_as_ushort(h1) << 16);
    l = (uint32_t)__bfloat16_as_ushort(l0) | ((uint32_t)__bfloat16_as_ushort(l1) << 16);
}

// ---------------------------------------------------------------------------
// Pre-split pass: H -> hi/lo bf16; W -> transposed hi/lo bf16
// ---------------------------------------------------------------------------
__global__ __launch_bounds__(256) void split_h(const float* __restrict__ H) {
    const size_t i = ((size_t)blockIdx.x * 256 + threadIdx.x) * 4;
    const float4 x = *reinterpret_cast<const float4*>(H + i);
    uint32_t h0, l0, h1, l1;
    split2(x.x, x.y, h0, l0);
    split2(x.z, x.w, h1, l1);
    *reinterpret_cast<uint2*>(&g_hh[i]) = make_uint2(h0, h1);
    *reinterpret_cast<uint2*>(&g_hl[i]) = make_uint2(l0, l1);
}

__global__ __launch_bounds__(256) void split_w(
    const float* __restrict__ Wq, const float* __restrict__ Wk,
    const float* __restrict__ Wv)
{
    __shared__ float t[32][33];
    const int z  = blockIdx.z;
    const float* __restrict__ W = (z == 0) ? Wq : (z == 1) ? Wk : Wv;
    const int n0 = blockIdx.x * 32;
    const int k0 = blockIdx.y * 32;
    const int tx = threadIdx.x & 31;
    const int ty = threadIdx.x >> 5;

    #pragma unroll
    for (int i = 0; i < 4; i++)
        t[ty + 8 * i][tx] = W[(size_t)(k0 + ty + 8 * i) * EMBED + n0 + tx];
    __syncthreads();

    const size_t zb = (size_t)z * EMBED * EMBED;
    #pragma unroll
    for (int i = 0; i < 4; i++) {
        const int n = ty + 8 * i;
        const float v = t[tx][n];
        __nv_bfloat16 h, l;
        split1(v, h, l);
        const size_t o = zb + (size_t)(n0 + n) * EMBED + k0 + tx;
        g_wth[o] = h;
        g_wtl[o] = l;
    }
}

// ---------------------------------------------------------------------------
// QKV GEMM v5: BK=32, 2-stage ring, one sync/iter, 80B rows (conflict-free).
// Grid (8, 64, 3), 128 threads (4 warps, 64x64 tiles). Dyn smem 80 KB.
// ---------------------------------------------------------------------------
#define RS5  80                    // row stride bytes (5 x 16B -> conflict-free)
#define STG5 (128 * RS5)           // 10240 B per stage per array
#define ARR5 (2 * STG5)            // 20480
#define GSM5 (4 * ARR5)            // 81920

__global__ __launch_bounds__(128, 2) void qkv_gemm5(
    const float* __restrict__ bq, const float* __restrict__ bk,
    const float* __restrict__ bv)
{
    extern __shared__ char dsm[];
    const uint32_t base = smem_u32(dsm);
    const uint32_t aAh = base;
    const uint32_t aAl = base + ARR5;
    const uint32_t aBh = base + 2 * ARR5;
    const uint32_t aBl = base + 3 * ARR5;

    const int tid  = threadIdx.x;
    const int wid  = tid >> 5;
    const int lane = tid & 31;

    const int z = blockIdx.z;
    const float* __restrict__ bias = (z == 0) ? bq : (z == 1) ? bk : bv;
    __nv_bfloat16* __restrict__ oh = (z == 0) ? g_qh : (z == 1) ? g_kh : g_vh;
    __nv_bfloat16* __restrict__ ol = (z == 0) ? g_ql : (z == 1) ? g_kl : g_vl;
    const float scale = (z == 0) ? 0.125f : 1.0f;

    const int m0 = blockIdx.y * 128;
    const int n0 = blockIdx.x * 128;
    const size_t zb = (size_t)z * EMBED * EMBED;

    const int wm = (wid >> 1) * 64;
    const int wn = (wid & 1) * 64;

    // staging: thread owns one row (0..127), 4x16B per array per chunk
    const uint32_t drow = (uint32_t)tid * RS5;
    const size_t arow = (size_t)(m0 + tid) * EMBED;
    const size_t brow = zb + (size_t)(n0 + tid) * EMBED;

    auto issue = [&](int c) {
        const uint32_t so = (uint32_t)(c & 1) * STG5 + drow;
        const size_t k = (size_t)c * 32;
        #pragma unroll
        for (int j = 0; j < 4; j++) {
            cpa16(aAh + so + 16 * j, g_hh + arow + k + 8 * j);
            cpa16(aAl + so + 16 * j, g_hl + arow + k + 8 * j);
            cpa16(aBh + so + 16 * j, g_wth + brow + k + 8 * j);
            cpa16(aBl + so + 16 * j, g_wtl + brow + k + 8 * j);
        }
        asm volatile("cp.async.commit_group;" ::: "memory");
    };

    float acc[4][8][4] = {};

    issue(0);

    const uint32_t kelA  = 16u * (lane >> 4);
    const uint32_t kelB  = 16u * ((lane >> 3) & 1);
    const uint32_t browF = (uint32_t)(8 * (lane >> 4) + (lane & 7));

    for (int c = 0; c < 32; c++) {
        asm volatile("cp.async.wait_group 0;" ::: "memory");
        __syncthreads();
        if (c < 31) issue(c + 1);   // other stage; its consumers passed sync

        const uint32_t so = (uint32_t)(c & 1) * STG5;
        #pragma unroll
        for (int g = 0; g < 2; g++) {
            const uint32_t gk = 32u * g;
            uint32_t ah[4][4], al[4][4];
            #pragma unroll
            for (int mi = 0; mi < 4; mi++) {
                const uint32_t ro = (uint32_t)(wm + mi * 16 + (lane & 15)) * RS5
                                  + gk + kelA;
                ldsm4(ah[mi], aAh + so + ro);
                ldsm4(al[mi], aAl + so + ro);
            }
            #pragma unroll
            for (int p = 0; p < 4; p++) {
                const uint32_t bo = (uint32_t)(wn + p * 16 + browF) * RS5
                                  + gk + kelB;
                uint32_t tbh[4], tbl[4];
                ldsm4(tbh, aBh + so + bo);
                ldsm4(tbl, aBl + so + bo);
                #pragma unroll
                for (int mi = 0; mi < 4; mi++) {
                    mma16816(acc[mi][2 * p],     ah[mi], tbh);
                    mma16816(acc[mi][2 * p],     ah[mi], tbl);
                    mma16816(acc[mi][2 * p],     al[mi], tbh);
                    mma16816(acc[mi][2 * p + 1], ah[mi], tbh + 2);
                    mma16816(acc[mi][2 * p + 1], ah[mi], tbl + 2);
                    mma16816(acc[mi][2 * p + 1], al[mi], tbh + 2);
                }
            }
        }
        __syncthreads();
    }

    // Epilogue: bias + scale, split to bf16 hi/lo (full stores, all z)
    #pragma unroll
    for (int mi = 0; mi < 4; mi++) {
        #pragma unroll
        for (int nj = 0; nj < 8; nj++) {
            const int r0  = m0 + wm + mi * 16 + (lane >> 2);
            const int col = n0 + wn + nj * 8 + (lane & 3) * 2;
            const float2 bv2 = *reinterpret_cast<const float2*>(&bias[col]);
            float v0 = (acc[mi][nj][0] + bv2.x) * scale;
            float v1 = (acc[mi][nj][1] + bv2.y) * scale;
            float v2 = (acc[mi][nj][2] + bv2.x) * scale;
            float v3 = (acc[mi][nj][3] + bv2.y) * scale;
            uint32_t h01, l01, h23, l23;
            split2(v0, v1, h01, l01);
            split2(v2, v3, h23, l23);
            *reinterpret_cast<uint32_t*>(&oh[(size_t)r0 * EMBED + col])       = h01;
            *reinterpret_cast<uint32_t*>(&ol[(size_t)r0 * EMBED + col])       = l01;
            *reinterpret_cast<uint32_t*>(&oh[(size_t)(r0 + 8) * EMBED + col]) = h23;
            *reinterpret_cast<uint32_t*>(&ol[(size_t)(r0 + 8) * EMBED + col]) = l23;
        }
    }
}

// ---------------------------------------------------------------------------
// Tensor-core flash attention (split-bf16 3-MMA QK^T and PV) — R14-proven.
// Fixed-max softmax + warp-uniform mask/chunk skip.
// ---------------------------------------------------------------------------
#define SKV 72
#define FMX 12.0f

__global__ __launch_bounds__(256) void fa_attn(float* __restrict__ out)
{
    __shared__ __align__(16) __nv_bfloat16 Kh[64 * SKV];
    __shared__ __align__(16) __nv_bfloat16 Kl[64 * SKV];
    __shared__ __align__(16) __nv_bfloat16 Vh[64 * SKV];
    __shared__ __align__(16) __nv_bfloat16 Vl[64 * SKV];

    const int tid  = threadIdx.x;
    const int wid  = tid >> 5;
    const int lane = tid & 31;
    const int q0   = blockIdx.x * 128;
    const int h    = blockIdx.y;
    const int b    = blockIdx.z;

    {
        const int r    = tid >> 1;
        const int half = tid & 1;
        const size_t gb = ((size_t)((b * SEQ + q0 + r) * NHEAD) + h) * HDIM + half * 32;
        __nv_bfloat16* dh = (r < 64 ? Kh : Kl) + (r & 63) * SKV + half * 32;
        __nv_bfloat16* dl = (r < 64 ? Vh : Vl) + (r & 63) * SKV + half * 32;
        #pragma unroll
        for (int i = 0; i < 4; i++) {
            *reinterpret_cast<uint4*>(dh + 8 * i) =
                *reinterpret_cast<const uint4*>(&g_qh[gb + 8 * i]);
            *reinterpret_cast<uint4*>(dl + 8 * i) =
                *reinterpret_cast<const uint4*>(&g_ql[gb + 8 * i]);
        }
    }
    __syncthreads();

    uint32_t qfh[4][4], qfl[4][4];
    {
        const int r = 16 * wid + (lane & 15);
        const __nv_bfloat16* sh = (r < 64 ? Kh : Kl) + (r & 63) * SKV;
        const __nv_bfloat16* sl = (r < 64 ? Vh : Vl) + (r & 63) * SKV;
        #pragma unroll
        for (int ks = 0; ks < 4; ks++) {
            const int kel = 16 * ks + 8 * (lane >> 4);
            ldsm4(qfh[ks], smem_u32(sh + kel));
            ldsm4(qfl[ks], smem_u32(sl + kel));
        }
    }
    __syncthreads();

    float O[8][4] = {};
    float l0 = 0.0f, l1 = 0.0f;
    const int qp0 = q0 + 16 * wid + (lane >> 2);
    const int qp1 = qp0 + 8;
    const int lo0 = qp0 - WIN < 0 ? 0 : qp0 - WIN;
    const int hi0 = qp0 + WIN > SEQ - 1 ? SEQ - 1 : qp0 + WIN;
    const int lo1 = qp1 - WIN < 0 ? 0 : qp1 - WIN;
    const int hi1 = qp1 + WIN > SEQ - 1 ? SEQ - 1 : qp1 + WIN;
    const int qpWmin = q0 + 16 * wid;
    const int qpWmax = qpWmin + 15;

    const int kc0  = q0 - WIN;
    const int srow = tid & 63;
    const int sq   = tid >> 6;

    uint4 pf[8];
    auto ldchunk = [&](int c) {
        const int kp = kc0 + c * 64 + srow;
        const bool in = (kp >= 0) && (kp < SEQ);
        const size_t gb = ((size_t)((b * SEQ + (in ? kp : 0)) * NHEAD) + h) * HDIM + sq * 16;
        const uint4 z = make_uint4(0u, 0u, 0u, 0u);
        pf[0] = in ? *reinterpret_cast<const uint4*>(&g_kh[gb])     : z;
        pf[1] = in ? *reinterpret_cast<const uint4*>(&g_kh[gb + 8]) : z;
        pf[2] = in ? *reinterpret_cast<const uint4*>(&g_kl[gb])     : z;
        pf[3] = in ? *reinterpret_cast<const uint4*>(&g_kl[gb + 8]) : z;
        pf[4] = in ? *reinterpret_cast<const uint4*>(&g_vh[gb])     : z;
        pf[5] = in ? *reinterpret_cast<const uint4*>(&g_vh[gb + 8]) : z;
        pf[6] = in ? *reinterpret_cast<const uint4*>(&g_vl[gb])     : z;
        pf[7] = in ? *reinterpret_cast<const uint4*>(&g_vl[gb + 8]) : z;
    };
    auto stchunk = [&]() {
        const int off = srow * SKV + sq * 16;
        *reinterpret_cast<uint4*>(&Kh[off])     = pf[0];
        *reinterpret_cast<uint4*>(&Kh[off + 8]) = pf[1];
        *reinterpret_cast<uint4*>(&Kl[off])     = pf[2];
        *reinterpret_cast<uint4*>(&Kl[off + 8]) = pf[3];
        *reinterpret_cast<uint4*>(&Vh[off])     = pf[4];
        *reinterpret_cast<uint4*>(&Vh[off + 8]) = pf[5];
        *reinterpret_cast<uint4*>(&Vl[off])     = pf[6];
        *reinterpret_cast<uint4*>(&Vl[off + 8]) = pf[7];
    };

    ldchunk(0);
    stchunk();
    __syncthreads();

    #pragma unroll 1
    for (int c = 0; c < 10; c++) {
        if (c < 9) ldchunk(c + 1);
        const int kc = kc0 + c * 64;

        const bool anyv = (kc + 63 >= qpWmin - WIN) && (kc <= qpWmax + WIN) &&
                          (kc + 63 >= 0) && (kc < SEQ);
        const bool fullv = (kc >= qpWmax - WIN) && (kc + 63 <= qpWmin + WIN) &&
                           (kc >= 0) && (kc + 63 < SEQ);

        if (anyv) {
            float S[8][4] = {};

            #pragma unroll
            for (int ks = 0; ks < 4; ks++) {
                uint32_t bh[8][2], bl[8][2];
                #pragma unroll
                for (int jp = 0; jp < 4; jp++) {
                    const int krow = 16 * jp + 8 * (lane >> 4) + (lane & 7);
                    const int col  = 16 * ks + 8 * ((lane >> 3) & 1);
                    uint32_t t4[4];
                    ldsm4(t4, smem_u32(&Kh[krow * SKV + col]));
                    bh[2 * jp][0] = t4[0]; bh[2 * jp][1] = t4[1];
                    bh[2 * jp + 1][0] = t4[2]; bh[2 * jp + 1][1] = t4[3];
                    ldsm4(t4, smem_u32(&Kl[krow * SKV + col]));
                    bl[2 * jp][0] = t4[0]; bl[2 * jp][1] = t4[1];
                    bl[2 * jp + 1][0] = t4[2]; bl[2 * jp + 1][1] = t4[3];
                }
                #pragma unroll
                for (int j = 0; j < 8; j++) {
                    mma16816(S[j], qfh[ks], bh[j]);
                    mma16816(S[j], qfh[ks], bl[j]);
                    mma16816(S[j], qfl[ks], bh[j]);
                }
            }

            if (!fullv) {
                #pragma unroll
                for (int j = 0; j < 8; j++) {
                    const int ka = kc + 8 * j + 2 * (lane & 3);
                    const int kb = ka + 1;
                    if (ka < lo0 || ka > hi0) S[j][0] = -1e30f;
                    if (kb < lo0 || kb > hi0) S[j][1] = -1e30f;
                    if (ka < lo1 || ka > hi1) S[j][2] = -1e30f;
                    if (kb < lo1 || kb > hi1) S[j][3] = -1e30f;
                }
            }

            float rs0 = 0.0f, rs1 = 0.0f;
            #pragma unroll
            for (int j = 0; j < 8; j++) {
                S[j][0] = __expf(S[j][0] - FMX);
                S[j][1] = __expf(S[j][1] - FMX);
                S[j][2] = __expf(S[j][2] - FMX);
                S[j][3] = __expf(S[j][3] - FMX);
                rs0 += S[j][0] + S[j][1];
                rs1 += S[j][2] + S[j][3];
            }
            rs0 += __shfl_xor_sync(0xffffffffu, rs0, 1);
            rs0 += __shfl_xor_sync(0xffffffffu, rs0, 2);
            rs1 += __shfl_xor_sync(0xffffffffu, rs1, 1);
            rs1 += __shfl_xor_sync(0xffffffffu, rs1, 2);
            l0 += rs0;
            l1 += rs1;

            #pragma unroll
            for (int ks = 0; ks < 4; ks++) {
                uint32_t pa[4], pb[4];
                split2(S[2 * ks][0],     S[2 * ks][1],     pa[0], pb[0]);
                split2(S[2 * ks][2],     S[2 * ks][3],     pa[1], pb[1]);
                split2(S[2 * ks + 1][0], S[2 * ks + 1][1], pa[2], pb[2]);
                split2(S[2 * ks + 1][2], S[2 * ks + 1][3], pa[3], pb[3]);

                uint32_t vh[8][2], vl[8][2];
                #pragma unroll
                for (int jp = 0; jp < 4; jp++) {
                    const int vrow = 16 * ks + (lane & 7) + 8 * ((lane >> 3) & 1);
                    const int vcol = 16 * jp + 8 * (lane >> 4);
                    uint32_t t4[4];
                    ldsm4t(t4, smem_u32(&Vh[vrow * SKV + vcol]));
                    vh[2 * jp][0] = t4[0]; vh[2 * jp][1] = t4[1];
                    vh[2 * jp + 1][0] = t4[2]; vh[2 * jp + 1][1] = t4[3];
                    ldsm4t(t4, smem_u32(&Vl[vrow * SKV + vcol]));
                    vl[2 * jp][0] = t4[0]; vl[2 * jp][1] = t4[1];
                    vl[2 * jp + 1][0] = t4[2]; vl[2 * jp + 1][1] = t4[3];
                }
                #pragma unroll
                for (int j = 0; j < 8; j++) {
                    mma16816(O[j], pa, vh[j]);
                    mma16816(O[j], pa, vl[j]);
                    mma16816(O[j], pb, vh[j]);
                }
            }
        }

        __syncthreads();
        if (c < 9) stchunk();
        __syncthreads();
    }

    const float inv0 = 1.0f / l0;
    const float inv1 = 1.0f / l1;
    #pragma unroll
    for (int j = 0; j < 8; j++) {
        const int d = 8 * j + 2 * (lane & 3);
        const size_t e = (size_t)h * HDIM + d;
        float2 w0 = make_float2(O[j][0] * inv0, O[j][1] * inv0);
        float2 w1 = make_float2(O[j][2] * inv1, O[j][3] * inv1);
        *reinterpret_cast<float2*>(&out[(size_t)(b * SEQ + qp0) * EMBED + e]) = w0;
        *reinterpret_cast<float2*>(&out[(size_t)(b * SEQ + qp1) * EMBED + e]) = w1;
    }
}

// ---------------------------------------------------------------------------
extern "C" void kernel_launch(void* const* d_in, const int* in_sizes, int n_in,
                              void* d_out, int out_size)
{
    const float* H  = (const float*)d_in[0];
    const float* Wq = (const float*)d_in[1];
    const float* bq = (const float*)d_in[2];
    const float* Wk = (const float*)d_in[3];
    const float* bk = (const float*)d_in[4];
    const float* Wv = (const float*)d_in[5];
    const float* bv = (const float*)d_in[6];
    float* out = (float*)d_out;

    cudaFuncSetAttribute(qkv_gemm5,
                         cudaFuncAttributeMaxDynamicSharedMemorySize, GSM5);

    split_h<<<(MTOT * EMBED) / (256 * 4), 256>>>(H);
    dim3 wgrid(EMBED / 32, EMBED / 32, 3);
    split_w<<<wgrid, 256>>>(Wq, Wk, Wv);

    dim3 ggrid(EMBED / 128, MTOT / 128, 3);   // (8, 64, 3)
    qkv_gemm5<<<ggrid, 128, GSM5>>>(bq, bk, bv);

    dim3 agrid(SEQ / 128, NHEAD, BSZ);        // (32, 16, 2)
    fa_attn<<<agrid, 256>>>(out);
}

// round 17
// speedup vs baseline: 1.3672x; 1.3672x over previous
#include <cuda_runtime.h>
#include <cuda_bf16.h>
#include <cstdint>

#define BSZ    2
#define SEQ    4096
#define EMBED  1024
#define NHEAD  16
#define HDIM   64
#define WIN    256
#define MTOT   (BSZ*SEQ)

// Split-bf16 Q/K/V scratch for attention
__device__ __nv_bfloat16 g_qh[(size_t)MTOT * EMBED];
__device__ __nv_bfloat16 g_ql[(size_t)MTOT * EMBED];
__device__ __nv_bfloat16 g_kh[(size_t)MTOT * EMBED];
__device__ __nv_bfloat16 g_kl[(size_t)MTOT * EMBED];
__device__ __nv_bfloat16 g_vh[(size_t)MTOT * EMBED];
__device__ __nv_bfloat16 g_vl[(size_t)MTOT * EMBED];
// Pre-split GEMM inputs: H [m][k]; W transposed [z][n][k]
__device__ __nv_bfloat16 g_hh[(size_t)MTOT * EMBED];
__device__ __nv_bfloat16 g_hl[(size_t)MTOT * EMBED];
__device__ __nv_bfloat16 g_wth[(size_t)3 * EMBED * EMBED];
__device__ __nv_bfloat16 g_wtl[(size_t)3 * EMBED * EMBED];

// ---------------------------------------------------------------------------
// Helpers
// ---------------------------------------------------------------------------
__device__ __forceinline__ uint32_t smem_u32(const void* p) {
    uint32_t a;
    asm("{ .reg .u64 t; cvta.to.shared.u64 t, %1; cvt.u32.u64 %0, t; }"
        : "=r"(a) : "l"(p));
    return a;
}
__device__ __forceinline__ void ldsm4(uint32_t* r, uint32_t addr) {
    asm volatile("ldmatrix.sync.aligned.m8n8.x4.shared.b16 {%0,%1,%2,%3}, [%4];"
        : "=r"(r[0]), "=r"(r[1]), "=r"(r[2]), "=r"(r[3]) : "r"(addr));
}
__device__ __forceinline__ void ldsm4t(uint32_t* r, uint32_t addr) {
    asm volatile("ldmatrix.sync.aligned.m8n8.x4.trans.shared.b16 {%0,%1,%2,%3}, [%4];"
        : "=r"(r[0]), "=r"(r[1]), "=r"(r[2]), "=r"(r[3]) : "r"(addr));
}
__device__ __forceinline__ void mma16816(float* c, const uint32_t* a,
                                         const uint32_t* b) {
    asm volatile(
        "mma.sync.aligned.m16n8k16.row.col.f32.bf16.bf16.f32 "
        "{%0,%1,%2,%3}, {%4,%5,%6,%7}, {%8,%9}, {%0,%1,%2,%3};"
        : "+f"(c[0]), "+f"(c[1]), "+f"(c[2]), "+f"(c[3])
        : "r"(a[0]), "r"(a[1]), "r"(a[2]), "r"(a[3]), "r"(b[0]), "r"(b[1]));
}
__device__ __forceinline__ void cpa16(uint32_t s, const void* g) {
    asm volatile(
        "{ .reg .u64 gp; cvta.to.global.u64 gp, %1;"
        "  cp.async.ca.shared.global [%0], [gp], 16; }"
        :: "r"(s), "l"(g));
}

__device__ __forceinline__ void split1(float x, __nv_bfloat16& h, __nv_bfloat16& l) {
    h = __float2bfloat16(x);
    l = __float2bfloat16(x - __bfloat162float(h));
}
__device__ __forceinline__ void split2(float x0, float x1, uint32_t& h, uint32_t& l) {
    __nv_bfloat16 h0, l0, h1, l1;
    split1(x0, h0, l0);
    split1(x1, h1, l1);
    h = (uint32_t)__bfloat16_as_ushort(h0) | ((uint32_t)__bfloat16_as_ushort(h1) << 16);
    l = (uint32_t)__bfloat16_as_ushort(l0) | ((uint32_t)__bfloat16_as_ushort(l1) << 16);
}

// ---------------------------------------------------------------------------
// Pre-split pass: H -> hi/lo bf16; W -> transposed hi/lo bf16
// ---------------------------------------------------------------------------
__global__ __launch_bounds__(256) void split_h(const float* __restrict__ H) {
    const size_t i = ((size_t)blockIdx.x * 256 + threadIdx.x) * 4;
    const float4 x = *reinterpret_cast<const float4*>(H + i);
    uint32_t h0, l0, h1, l1;
    split2(x.x, x.y, h0, l0);
    split2(x.z, x.w, h1, l1);
    *reinterpret_cast<uint2*>(&g_hh[i]) = make_uint2(h0, h1);
    *reinterpret_cast<uint2*>(&g_hl[i]) = make_uint2(l0, l1);
}

__global__ __launch_bounds__(256) void split_w(
    const float* __restrict__ Wq, const float* __restrict__ Wk,
    const float* __restrict__ Wv)
{
    __shared__ float t[32][33];
    const int z  = blockIdx.z;
    const float* __restrict__ W = (z == 0) ? Wq : (z == 1) ? Wk : Wv;
    const int n0 = blockIdx.x * 32;
    const int k0 = blockIdx.y * 32;
    const int tx = threadIdx.x & 31;
    const int ty = threadIdx.x >> 5;

    #pragma unroll
    for (int i = 0; i < 4; i++)
        t[ty + 8 * i][tx] = W[(size_t)(k0 + ty + 8 * i) * EMBED + n0 + tx];
    __syncthreads();

    const size_t zb = (size_t)z * EMBED * EMBED;
    #pragma unroll
    for (int i = 0; i < 4; i++) {
        const int n = ty + 8 * i;
        const float v = t[tx][n];
        __nv_bfloat16 h, l;
        split1(v, h, l);
        const size_t o = zb + (size_t)(n0 + n) * EMBED + k0 + tx;
        g_wth[o] = h;
        g_wtl[o] = l;
    }
}

// ---------------------------------------------------------------------------
// QKV GEMM v6: R14-proven v4 skeleton, extended to 4-stage ring, wait_group 2.
// Grid (8, 64, 3), 128 threads (4 warps, 64x64 tiles). BK=16. Dyn smem 96 KB.
// ---------------------------------------------------------------------------
#define STG6 6144                 // per-stage bytes per array (128*48)
#define ARR6 (4 * STG6)           // per-array bytes (24576)
#define GSM6 (4 * ARR6)           // 98304

__global__ __launch_bounds__(128, 2) void qkv_gemm6(
    const float* __restrict__ bq, const float* __restrict__ bk,
    const float* __restrict__ bv)
{
    extern __shared__ char dsm[];
    const uint32_t base = smem_u32(dsm);
    const uint32_t aAh = base;
    const uint32_t aAl = base + ARR6;
    const uint32_t aBh = base + 2 * ARR6;
    const uint32_t aBl = base + 3 * ARR6;

    const int tid  = threadIdx.x;
    const int wid  = tid >> 5;
    const int lane = tid & 31;

    const int z = blockIdx.z;
    const float* __restrict__ bias = (z == 0) ? bq : (z == 1) ? bk : bv;
    __nv_bfloat16* __restrict__ oh = (z == 0) ? g_qh : (z == 1) ? g_kh : g_vh;
    __nv_bfloat16* __restrict__ ol = (z == 0) ? g_ql : (z == 1) ? g_kl : g_vl;
    const float scale = (z == 0) ? 0.125f : 1.0f;

    const int m0 = blockIdx.y * 128;
    const int n0 = blockIdx.x * 128;
    const size_t zb = (size_t)z * EMBED * EMBED;

    const int wm = (wid >> 1) * 64;
    const int wn = (wid & 1) * 64;

    const int rowT  = tid >> 1;        // 0..63
    const int halfT = tid & 1;
    const uint32_t doff0 = (uint32_t)(rowT * 48 + halfT * 16);
    const uint32_t doff1 = (uint32_t)((rowT + 64) * 48 + halfT * 16);
    const size_t arow0 = (size_t)(m0 + rowT) * EMBED + halfT * 8;
    const size_t arow1 = (size_t)(m0 + rowT + 64) * EMBED + halfT * 8;
    const size_t brow0 = zb + (size_t)(n0 + rowT) * EMBED + halfT * 8;
    const size_t brow1 = zb + (size_t)(n0 + rowT + 64) * EMBED + halfT * 8;

    auto issue = [&](int c) {
        const uint32_t so = (uint32_t)(c & 3) * STG6;
        const size_t k = (size_t)c * 16;
        cpa16(aAh + so + doff0, g_hh + arow0 + k);
        cpa16(aAh + so + doff1, g_hh + arow1 + k);
        cpa16(aAl + so + doff0, g_hl + arow0 + k);
        cpa16(aAl + so + doff1, g_hl + arow1 + k);
        cpa16(aBh + so + doff0, g_wth + brow0 + k);
        cpa16(aBh + so + doff1, g_wth + brow1 + k);
        cpa16(aBl + so + doff0, g_wtl + brow0 + k);
        cpa16(aBl + so + doff1, g_wtl + brow1 + k);
        asm volatile("cp.async.commit_group;" ::: "memory");
    };

    float acc[4][8][4] = {};

    issue(0);
    issue(1);
    issue(2);

    const uint32_t kelA  = 16u * (lane >> 4);
    const uint32_t kelB  = 16u * ((lane >> 3) & 1);
    const uint32_t browF = (uint32_t)(8 * (lane >> 4) + (lane & 7));

    for (int c = 0; c < 64; c++) {
        if (c <= 61)      asm volatile("cp.async.wait_group 2;" ::: "memory");
        else if (c == 62) asm volatile("cp.async.wait_group 1;" ::: "memory");
        else              asm volatile("cp.async.wait_group 0;" ::: "memory");
        __syncthreads();
        if (c <= 60) issue(c + 3);   // stage (c+3)&3: consumers done pre-sync

        const uint32_t so = (uint32_t)(c & 3) * STG6;
        uint32_t ah[4][4], al[4][4];
        #pragma unroll
        for (int mi = 0; mi < 4; mi++) {
            const uint32_t ro = (uint32_t)(wm + mi * 16 + (lane & 15)) * 48 + kelA;
            ldsm4(ah[mi], aAh + so + ro);
            ldsm4(al[mi], aAl + so + ro);
        }
        #pragma unroll
        for (int p = 0; p < 4; p++) {
            const uint32_t bo = (uint32_t)(wn + p * 16 + browF) * 48 + kelB;
            uint32_t tbh[4], tbl[4];
            ldsm4(tbh, aBh + so + bo);
            ldsm4(tbl, aBl + so + bo);
            #pragma unroll
            for (int mi = 0; mi < 4; mi++) {
                mma16816(acc[mi][2 * p],     ah[mi], tbh);
                mma16816(acc[mi][2 * p],     ah[mi], tbl);
                mma16816(acc[mi][2 * p],     al[mi], tbh);
                mma16816(acc[mi][2 * p + 1], ah[mi], tbh + 2);
                mma16816(acc[mi][2 * p + 1], ah[mi], tbl + 2);
                mma16816(acc[mi][2 * p + 1], al[mi], tbh + 2);
            }
        }
    }

    // Epilogue: bias + scale, split to bf16 hi/lo
    #pragma unroll
    for (int mi = 0; mi < 4; mi++) {
        #pragma unroll
        for (int nj = 0; nj < 8; nj++) {
            const int r0  = m0 + wm + mi * 16 + (lane >> 2);
            const int col = n0 + wn + nj * 8 + (lane & 3) * 2;
            const float2 bv2 = *reinterpret_cast<const float2*>(&bias[col]);
            float v0 = (acc[mi][nj][0] + bv2.x) * scale;
            float v1 = (acc[mi][nj][1] + bv2.y) * scale;
            float v2 = (acc[mi][nj][2] + bv2.x) * scale;
            float v3 = (acc[mi][nj][3] + bv2.y) * scale;
            uint32_t h01, l01, h23, l23;
            split2(v0, v1, h01, l01);
            split2(v2, v3, h23, l23);
            *reinterpret_cast<uint32_t*>(&oh[(size_t)r0 * EMBED + col])       = h01;
            *reinterpret_cast<uint32_t*>(&ol[(size_t)r0 * EMBED + col])       = l01;
            *reinterpret_cast<uint32_t*>(&oh[(size_t)(r0 + 8) * EMBED + col]) = h23;
            *reinterpret_cast<uint32_t*>(&ol[(size_t)(r0 + 8) * EMBED + col]) = l23;
        }
    }
}

// ---------------------------------------------------------------------------
// Tensor-core flash attention (split-bf16 3-MMA QK^T and PV, R14 numerics).
// K/V via 3-stage cp.async ring: one sync per chunk, no register staging.
// Out-of-range keys load clamped row-0 values — always window-masked.
// ---------------------------------------------------------------------------
#define SKVB   144                      // row stride bytes (72 bf16)
#define KV_ARR (64 * SKVB)              // 9216 per array per stage
#define KV_STG (4 * KV_ARR)             // 36864 per stage (Kh|Kl|Vh|Vl)
#define FA_SMEM (3 * KV_STG)            // 110592
#define FMX 12.0f

__global__ __launch_bounds__(256) void fa_attn(float* __restrict__ out)
{
    extern __shared__ char dsm[];
    const uint32_t base = smem_u32(dsm);

    const int tid  = threadIdx.x;
    const int wid  = tid >> 5;
    const int lane = tid & 31;
    const int q0   = blockIdx.x * 128;
    const int h    = blockIdx.y;
    const int b    = blockIdx.z;

    // ---- Stage Q tile into stage-0 block, extract warp frags ----
    {
        const int r    = tid >> 1;
        const int half = tid & 1;
        const size_t gb = ((size_t)((b * SEQ + q0 + r) * NHEAD) + h) * HDIM + half * 32;
        char* dh = dsm + (r < 64 ? 0 : KV_ARR)          + (r & 63) * SKVB + half * 64;
        char* dl = dsm + (r < 64 ? 2 * KV_ARR : 3 * KV_ARR) + (r & 63) * SKVB + half * 64;
        #pragma unroll
        for (int i = 0; i < 4; i++) {
            *reinterpret_cast<uint4*>(dh + 16 * i) =
                *reinterpret_cast<const uint4*>(&g_qh[gb + 8 * i]);
            *reinterpret_cast<uint4*>(dl + 16 * i) =
                *reinterpret_cast<const uint4*>(&g_ql[gb + 8 * i]);
        }
    }
    __syncthreads();

    uint32_t qfh[4][4], qfl[4][4];
    {
        const int r = 16 * wid + (lane & 15);
        const uint32_t sh = base + (r < 64 ? 0 : KV_ARR) + (r & 63) * SKVB;
        const uint32_t sl = base + (r < 64 ? 2 * KV_ARR : 3 * KV_ARR) + (r & 63) * SKVB;
        #pragma unroll
        for (int ks = 0; ks < 4; ks++) {
            const uint32_t kel = 32u * ks + 16u * (lane >> 4);
            ldsm4(qfh[ks], sh + kel);
            ldsm4(qfl[ks], sl + kel);
        }
    }
    __syncthreads();

    float O[8][4] = {};
    float l0 = 0.0f, l1 = 0.0f;
    const int qp0 = q0 + 16 * wid + (lane >> 2);
    const int qp1 = qp0 + 8;
    const int lo0 = qp0 - WIN < 0 ? 0 : qp0 - WIN;
    const int hi0 = qp0 + WIN > SEQ - 1 ? SEQ - 1 : qp0 + WIN;
    const int lo1 = qp1 - WIN < 0 ? 0 : qp1 - WIN;
    const int hi1 = qp1 + WIN > SEQ - 1 ? SEQ - 1 : qp1 + WIN;
    const int qpWmin = q0 + 16 * wid;
    const int qpWmax = qpWmin + 15;

    const int kc0  = q0 - WIN;
    const int srow = tid & 63;
    const int sq   = tid >> 6;       // 0..3 -> 32B slice

    auto ldchunk = [&](int c) {
        const int kp = kc0 + c * 64 + srow;
        const int kpc = (kp >= 0 && kp < SEQ) ? kp : 0;   // clamped (masked later)
        const size_t gb = ((size_t)((b * SEQ + kpc) * NHEAD) + h) * HDIM + sq * 16;
        const uint32_t so = base + (uint32_t)(c % 3) * KV_STG + srow * SKVB + sq * 32;
        cpa16(so,                  g_kh + gb);
        cpa16(so + 16,             g_kh + gb + 8);
        cpa16(so + KV_ARR,         g_kl + gb);
        cpa16(so + KV_ARR + 16,    g_kl + gb + 8);
        cpa16(so + 2 * KV_ARR,     g_vh + gb);
        cpa16(so + 2 * KV_ARR + 16, g_vh + gb + 8);
        cpa16(so + 3 * KV_ARR,     g_vl + gb);
        cpa16(so + 3 * KV_ARR + 16, g_vl + gb + 8);
        asm volatile("cp.async.commit_group;" ::: "memory");
    };

    ldchunk(0);
    ldchunk(1);

    #pragma unroll 1
    for (int c = 0; c < 10; c++) {
        if (c < 9) asm volatile("cp.async.wait_group 1;" ::: "memory");
        else       asm volatile("cp.async.wait_group 0;" ::: "memory");
        __syncthreads();
        if (c < 8) ldchunk(c + 2);   // stage (c+2)%3: readers done pre-sync

        const int kc = kc0 + c * 64;
        const uint32_t sb = base + (uint32_t)(c % 3) * KV_STG;

        const bool anyv = (kc + 63 >= qpWmin - WIN) && (kc <= qpWmax + WIN) &&
                          (kc + 63 >= 0) && (kc < SEQ);
        const bool fullv = (kc >= qpWmax - WIN) && (kc + 63 <= qpWmin + WIN) &&
                           (kc >= 0) && (kc + 63 < SEQ);

        if (anyv) {
            float S[8][4] = {};

            #pragma unroll
            for (int ks = 0; ks < 4; ks++) {
                uint32_t bh[8][2], bl[8][2];
                #pragma unroll
                for (int jp = 0; jp < 4; jp++) {
                    const uint32_t krow = (uint32_t)(16 * jp + 8 * (lane >> 4) + (lane & 7));
                    const uint32_t col  = 32u * ks + 16u * ((lane >> 3) & 1);
                    uint32_t t4[4];
                    ldsm4(t4, sb + krow * SKVB + col);
                    bh[2 * jp][0] = t4[0]; bh[2 * jp][1] = t4[1];
                    bh[2 * jp + 1][0] = t4[2]; bh[2 * jp + 1][1] = t4[3];
                    ldsm4(t4, sb + KV_ARR + krow * SKVB + col);
                    bl[2 * jp][0] = t4[0]; bl[2 * jp][1] = t4[1];
                    bl[2 * jp + 1][0] = t4[2]; bl[2 * jp + 1][1] = t4[3];
                }
                #pragma unroll
                for (int j = 0; j < 8; j++) {
                    mma16816(S[j], qfh[ks], bh[j]);
                    mma16816(S[j], qfh[ks], bl[j]);
                    mma16816(S[j], qfl[ks], bh[j]);
                }
            }

            if (!fullv) {
                #pragma unroll
                for (int j = 0; j < 8; j++) {
                    const int ka = kc + 8 * j + 2 * (lane & 3);
                    const int kb = ka + 1;
                    if (ka < lo0 || ka > hi0) S[j][0] = -1e30f;
                    if (kb < lo0 || kb > hi0) S[j][1] = -1e30f;
                    if (ka < lo1 || ka > hi1) S[j][2] = -1e30f;
                    if (kb < lo1 || kb > hi1) S[j][3] = -1e30f;
                }
            }

            float rs0 = 0.0f, rs1 = 0.0f;
            #pragma unroll
            for (int j = 0; j < 8; j++) {
                S[j][0] = __expf(S[j][0] - FMX);
                S[j][1] = __expf(S[j][1] - FMX);
                S[j][2] = __expf(S[j][2] - FMX);
                S[j][3] = __expf(S[j][3] - FMX);
                rs0 += S[j][0] + S[j][1];
                rs1 += S[j][2] + S[j][3];
            }
            rs0 += __shfl_xor_sync(0xffffffffu, rs0, 1);
            rs0 += __shfl_xor_sync(0xffffffffu, rs0, 2);
            rs1 += __shfl_xor_sync(0xffffffffu, rs1, 1);
            rs1 += __shfl_xor_sync(0xffffffffu, rs1, 2);
            l0 += rs0;
            l1 += rs1;

            #pragma unroll
            for (int ks = 0; ks < 4; ks++) {
                uint32_t pa[4], pb[4];
                split2(S[2 * ks][0],     S[2 * ks][1],     pa[0], pb[0]);
                split2(S[2 * ks][2],     S[2 * ks][3],     pa[1], pb[1]);
                split2(S[2 * ks + 1][0], S[2 * ks + 1][1], pa[2], pb[2]);
                split2(S[2 * ks + 1][2], S[2 * ks + 1][3], pa[3], pb[3]);

                uint32_t vh[8][2], vl[8][2];
                #pragma unroll
                for (int jp = 0; jp < 4; jp++) {
                    const uint32_t vrow = (uint32_t)(16 * ks + (lane & 7) + 8 * ((lane >> 3) & 1));
                    const uint32_t vcol = 32u * jp + 16u * (lane >> 4);
                    uint32_t t4[4];
                    ldsm4t(t4, sb + 2 * KV_ARR + vrow * SKVB + vcol);
                    vh[2 * jp][0] = t4[0]; vh[2 * jp][1] = t4[1];
                    vh[2 * jp + 1][0] = t4[2]; vh[2 * jp + 1][1] = t4[3];
                    ldsm4t(t4, sb + 3 * KV_ARR + vrow * SKVB + vcol);
                    vl[2 * jp][0] = t4[0]; vl[2 * jp][1] = t4[1];
                    vl[2 * jp + 1][0] = t4[2]; vl[2 * jp + 1][1] = t4[3];
                }
                #pragma unroll
                for (int j = 0; j < 8; j++) {
                    mma16816(O[j], pa, vh[j]);
                    mma16816(O[j], pa, vl[j]);
                    mma16816(O[j], pb, vh[j]);
                }
            }
        }
    }

    const float inv0 = 1.0f / l0;
    const float inv1 = 1.0f / l1;
    #pragma unroll
    for (int j = 0; j < 8; j++) {
        const int d = 8 * j + 2 * (lane & 3);
        const size_t e = (size_t)h * HDIM + d;
        float2 w0 = make_float2(O[j][0] * inv0, O[j][1] * inv0);
        float2 w1 = make_float2(O[j][2] * inv1, O[j][3] * inv1);
        *reinterpret_cast<float2*>(&out[(size_t)(b * SEQ + qp0) * EMBED + e]) = w0;
        *reinterpret_cast<float2*>(&out[(size_t)(b * SEQ + qp1) * EMBED + e]) = w1;
    }
}

// ---------------------------------------------------------------------------
extern "C" void kernel_launch(void* const* d_in, const int* in_sizes, int n_in,
                              void* d_out, int out_size)
{
    const float* H  = (const float*)d_in[0];
    const float* Wq = (const float*)d_in[1];
    const float* bq = (const float*)d_in[2];
    const float* Wk = (const float*)d_in[3];
    const float* bk = (const float*)d_in[4];
    const float* Wv = (const float*)d_in[5];
    const float* bv = (const float*)d_in[6];
    float* out = (float*)d_out;

    cudaFuncSetAttribute(qkv_gemm6,
                         cudaFuncAttributeMaxDynamicSharedMemorySize, GSM6);
    cudaFuncSetAttribute(fa_attn,
                         cudaFuncAttributeMaxDynamicSharedMemorySize, FA_SMEM);

    split_h<<<(MTOT * EMBED) / (256 * 4), 256>>>(H);
    dim3 wgrid(EMBED / 32, EMBED / 32, 3);
    split_w<<<wgrid, 256>>>(Wq, Wk, Wv);

    dim3 ggrid(EMBED / 128, MTOT / 128, 3);   // (8, 64, 3)
    qkv_gemm6<<<ggrid, 128, GSM6>>>(bq, bk, bv);

    dim3 agrid(SEQ / 128, NHEAD, BSZ);        // (32, 16, 2)
    fa_attn<<<agrid, 256, FA_SMEM>>>(out);
}